// round 4
// baseline (speedup 1.0000x reference)
#include <cuda_runtime.h>
#include <cuda_bf16.h>
#include <math.h>

// Problem constants (fixed by setup_inputs)
#define BS    16
#define T     1024
#define DF    80          // feature dim
#define DF4   20          // as float4
#define SIZE  4096
#define TPB   128         // 1 thread = 1 output row (b,s)

// Device scratch (allocation-free): sorted centers + permutation per batch
__device__ float g_cs[BS * T];
__device__ int   g_ci[BS * T];

// ---------------------------------------------------------------------------
// Kernel 1: fp32 cumsum replicating jax.lax.associative_scan's exact
// association tree (what jnp.cumsum lowers to on CPU/GPU), then centers,
// then bitonic sort by c so the main kernel sees a monotonic array for
// every batch (incl. batch 0, whose row is zeroed by the reference).
// ---------------------------------------------------------------------------
__global__ void prep_kernel(const float* __restrict__ d) {
    __shared__ float r[2047];
    __shared__ float s[2047];
    __shared__ float cv[T];
    __shared__ int   ci[T];
    const int b = blockIdx.x;
    const int t = threadIdx.x;

    const float v = d[b * T + t];
    r[t] = v;
    __syncthreads();

    // upsweep: pair sums, exactly the reference's association
    {
        int off = 0, n = T;
        while (n > 1) {
            int noff = off + n;
            if (t < (n >> 1))
                r[noff + t] = __fadd_rn(r[off + 2 * t], r[off + 2 * t + 1]);
            __syncthreads();
            off = noff; n >>= 1;
        }
    }
    // downsweep
    if (t == 0) s[2046] = r[2046];
    __syncthreads();
    #pragma unroll
    for (int L = 9; L >= 0; --L) {
        const int n    = T >> L;
        const int off  = 2048 - (2048 >> L);
        const int offn = 2048 - (2048 >> (L + 1));
        if (t < n) {
            float val;
            if (t == 0)        val = r[off];
            else if (t & 1)    val = s[offn + (t >> 1)];
            else               val = __fadd_rn(s[offn + (t >> 1) - 1], r[off + t]);
            s[off + t] = val;
        }
        __syncthreads();
    }
    // s[0..1023] = inclusive fp32 cumsum of d[b], matching the reference tree

    float cs;
    if (b == 0)       cs = 0.0f;         // reference zeroes whole batch-0 row
    else if (t == 0)  cs = s[T - 1];     // rolled: total sum
    else              cs = s[t - 1];     // exclusive prefix
    cv[t] = __fadd_rn(0.5f * v, cs);     // c = d/2 + cs (d/2 exact in fp32)
    ci[t] = t;
    __syncthreads();

    // in-place bitonic sort of (cv, ci) ascending by cv
    for (int k = 2; k <= T; k <<= 1) {
        for (int j = k >> 1; j > 0; j >>= 1) {
            int i = t ^ j;
            if (i > t) {
                bool up = ((t & k) == 0);
                float a = cv[t], bb = cv[i];
                if ((a > bb) == up) {
                    cv[t] = bb; cv[i] = a;
                    int tmp = ci[t]; ci[t] = ci[i]; ci[i] = tmp;
                }
            }
            __syncthreads();
        }
    }
    g_cs[b * T + t] = cv[t];
    g_ci[b * T + t] = ci[t];
}

// ---------------------------------------------------------------------------
// Kernel 2: windowed softmax over SORTED centers, QUANTIZATION-FAITHFUL:
// every score is computed exactly as the reference does in fp32 —
//   dt = fsub(t, c); sq = fmul(dt, dt); score = -fdiv(sq, 2*sigma^2)
// (explicit intrinsics so ptxas cannot fuse the square into an FMA; the
// reference's rounded dt^2 has ulp=2 at large s and MUST be reproduced).
// score_max = -fdiv(min(round(dA^2), round(dB^2)), 2s^2) equals the
// reference's global max by monotonicity of rounding. Then
// e = fsub(score, score_max) is bit-identical to the reference exponent.
// ---------------------------------------------------------------------------
__global__ void __launch_bounds__(TPB) alignment_kernel(
    const float* __restrict__ h,      // [BS, T, DF]
    const float* __restrict__ sigma,  // [1]
    float* __restrict__ out)          // [BS, SIZE, DF]
{
    __shared__ float c_sh[T];
    __shared__ int   i_sh[T];
    const int b = blockIdx.y;
    const int s = blockIdx.x * TPB + threadIdx.x;

    for (int i = threadIdx.x; i < T; i += TPB) {
        c_sh[i] = g_cs[b * T + i];
        i_sh[i] = g_ci[b * T + i];
    }
    __syncthreads();

    const float sg     = sigma[0];
    const float two_s2 = 2.0f * sg * sg;
    const float tval   = (float)s + 1.5f;

    // first index in [0,T) with c_sh[k] > x (T if none) — c_sh sorted
    auto lower = [&](float x) -> int {
        int lo = 0, hi = T;
        while (lo < hi) {
            int m = (lo + hi) >> 1;
            if (c_sh[m] > x) hi = m; else lo = m + 1;
        }
        return lo;
    };

    // exact global max score from the two crossing candidates,
    // with the SAME rounded-square quantization as the reference
    int kc = lower(tval);
    int kA = kc < (T - 1) ? kc : (T - 1);
    int kB = (kc - 1) > 0 ? (kc - 1) : 0;
    float dA  = __fsub_rn(tval, c_sh[kA]);
    float dB  = __fsub_rn(tval, c_sh[kB]);
    float sqA = __fmul_rn(dA, dA);
    float sqB = __fmul_rn(dB, dB);
    float sqmin = fminf(sqA, sqB);
    const float score_max = -__fdiv_rn(sqmin, two_s2);

    // window: e > -24  <=>  sq < sqmin + 24*two_s2 (margin absorbs ulp jitter)
    const float rr  = sqrtf(sqmin + 24.0f * two_s2);
    int klo = lower(tval - rr);        // first c >  t-r
    int khi = lower(tval + rr) - 1;    // last  c <= t+r

    // warp union (lanes are consecutive s -> union is tight)
    int wlo = __reduce_min_sync(0xFFFFFFFFu, klo);
    int whi = __reduce_max_sync(0xFFFFFFFFu, khi);

    const float4* __restrict__ h4 = (const float4*)h;
    const size_t  bOff = (size_t)b * T;

    float  l = 0.0f;
    float4 acc[DF4];
    #pragma unroll
    for (int j = 0; j < DF4; ++j) acc[j] = make_float4(0.f, 0.f, 0.f, 0.f);

    // main loop: k warp-uniform -> idx warp-uniform -> broadcast LDG.128s
    for (int k = wlo; k <= whi; ++k) {
        float dt = __fsub_rn(tval, c_sh[k]);
        float sq = __fmul_rn(dt, dt);              // rounded square, like ref
        float sc = -__fdiv_rn(sq, two_s2);         // ref's division
        float e  = __fsub_rn(sc, score_max);       // ref softmax shift
        float w  = __expf(e);                      // <= 1 always
        l += w;
        const int id = i_sh[k];
        const float4* hr = h4 + (bOff + id) * DF4;
        #pragma unroll
        for (int j = 0; j < DF4; ++j) {
            float4 hv = hr[j];
            acc[j].x += w * hv.x; acc[j].y += w * hv.y;
            acc[j].z += w * hv.z; acc[j].w += w * hv.w;
        }
    }

    const float linv = 1.0f / l;
    float4* o = (float4*)out + ((size_t)b * SIZE + s) * DF4;
    #pragma unroll
    for (int j = 0; j < DF4; ++j) {
        float4 v;
        v.x = acc[j].x * linv; v.y = acc[j].y * linv;
        v.z = acc[j].z * linv; v.w = acc[j].w * linv;
        o[j] = v;
    }
}

// ---------------------------------------------------------------------------
extern "C" void kernel_launch(void* const* d_in, const int* in_sizes, int n_in,
                              void* d_out, int out_size) {
    const float* h     = (const float*)d_in[0];  // [16,1024,80]
    const float* d     = (const float*)d_in[1];  // [16,1024]
    const float* sigma = (const float*)d_in[2];  // [1]

    prep_kernel<<<BS, T>>>(d);
    dim3 grid(SIZE / TPB, BS);
    alignment_kernel<<<grid, TPB>>>(h, sigma, (float*)d_out);
}

// round 5
// speedup vs baseline: 2.9095x; 2.9095x over previous
#include <cuda_runtime.h>
#include <cuda_bf16.h>
#include <math.h>

// Problem constants (fixed by setup_inputs)
#define BS    16
#define T     1024
#define DF    80          // feature dim
#define DF4   20          // as float4
#define SIZE  4096
#define TPB   256         // 4 lanes per row -> 64 rows per block
#define RPB   64          // rows per block
#define TPAD  4           // padding entries (+inf centers) for chunk-of-4 loop

// Device scratch (allocation-free): sorted centers + permutation per batch
__device__ float g_cs[BS * T];
__device__ int   g_ci[BS * T];

// ---------------------------------------------------------------------------
// Kernel 1: fp32 cumsum replicating jax.lax.associative_scan's association
// tree, then centers, then bitonic sort by c (monotone for every batch,
// incl. batch 0 whose cumsum row is zeroed by the reference).
// ---------------------------------------------------------------------------
__global__ void prep_kernel(const float* __restrict__ d) {
    __shared__ float r[2047];
    __shared__ float s[2047];
    __shared__ float cv[T];
    __shared__ int   ci[T];
    const int b = blockIdx.x;
    const int t = threadIdx.x;

    const float v = d[b * T + t];
    r[t] = v;
    __syncthreads();

    // upsweep: pair sums
    {
        int off = 0, n = T;
        while (n > 1) {
            int noff = off + n;
            if (t < (n >> 1))
                r[noff + t] = __fadd_rn(r[off + 2 * t], r[off + 2 * t + 1]);
            __syncthreads();
            off = noff; n >>= 1;
        }
    }
    // downsweep
    if (t == 0) s[2046] = r[2046];
    __syncthreads();
    #pragma unroll
    for (int L = 9; L >= 0; --L) {
        const int n    = T >> L;
        const int off  = 2048 - (2048 >> L);
        const int offn = 2048 - (2048 >> (L + 1));
        if (t < n) {
            float val;
            if (t == 0)        val = r[off];
            else if (t & 1)    val = s[offn + (t >> 1)];
            else               val = __fadd_rn(s[offn + (t >> 1) - 1], r[off + t]);
            s[off + t] = val;
        }
        __syncthreads();
    }

    float cs;
    if (b == 0)       cs = 0.0f;         // reference zeroes whole batch-0 row
    else if (t == 0)  cs = s[T - 1];     // rolled: total sum
    else              cs = s[t - 1];     // exclusive prefix
    cv[t] = __fadd_rn(0.5f * v, cs);
    ci[t] = t;
    __syncthreads();

    // in-place bitonic sort of (cv, ci) ascending by cv
    for (int k = 2; k <= T; k <<= 1) {
        for (int j = k >> 1; j > 0; j >>= 1) {
            int i = t ^ j;
            if (i > t) {
                bool up = ((t & k) == 0);
                float a = cv[t], bb = cv[i];
                if ((a > bb) == up) {
                    cv[t] = bb; cv[i] = a;
                    int tmp = ci[t]; ci[t] = ci[i]; ci[i] = tmp;
                }
            }
            __syncthreads();
        }
    }
    g_cs[b * T + t] = cv[t];
    g_ci[b * T + t] = ci[t];
}

// ---------------------------------------------------------------------------
// Kernel 2: windowed softmax, quantization-faithful scoring (as R4):
//   dt = fsub(t,c); sq = fmul(dt,dt); sc = -fdiv(sq, 2s^2); e = fsub(sc, max)
// Layout: QUAD per row — lane f of a quad owns float4 columns {f,f+4,...,f+16}
// (5 float4 accumulators). 8 consecutive rows per warp. The weight chain for
// 4 consecutive k's is computed one-k-per-lane and exchanged via shfl_xor
// within the quad (exp/div count unchanged, serial chain quartered).
// Padded centers (+inf) make out-of-range k's contribute exactly w = 0.
// ---------------------------------------------------------------------------
__global__ void __launch_bounds__(TPB) alignment_kernel(
    const float* __restrict__ h,      // [BS, T, DF]
    const float* __restrict__ sigma,  // [1]
    float* __restrict__ out)          // [BS, SIZE, DF]
{
    __shared__ float c_sh[T + TPAD];
    __shared__ int   i_sh[T + TPAD];
    const int b    = blockIdx.y;
    const int tid  = threadIdx.x;
    const int f    = tid & 3;         // lane-in-quad = feature group
    const int row  = tid >> 2;        // row-in-block
    const int s    = blockIdx.x * RPB + row;

    for (int i = tid; i < T; i += TPB) {
        c_sh[i] = g_cs[b * T + i];
        i_sh[i] = g_ci[b * T + i];
    }
    if (tid < TPAD) { c_sh[T + tid] = INFINITY; i_sh[T + tid] = 0; }
    __syncthreads();

    const float sg     = sigma[0];
    const float two_s2 = 2.0f * sg * sg;
    const float tval   = (float)s + 1.5f;

    // first index in [0,T) with c_sh[k] > x (T if none) — c_sh sorted
    auto lower = [&](float x) -> int {
        int lo = 0, hi = T;
        while (lo < hi) {
            int m = (lo + hi) >> 1;
            if (c_sh[m] > x) hi = m; else lo = m + 1;
        }
        return lo;
    };

    // exact global max score (reference-rounded squares)
    int kc = lower(tval);
    int kA = kc < (T - 1) ? kc : (T - 1);
    int kB = (kc - 1) > 0 ? (kc - 1) : 0;
    float dA  = __fsub_rn(tval, c_sh[kA]);
    float dB  = __fsub_rn(tval, c_sh[kB]);
    float sqA = __fmul_rn(dA, dA);
    float sqB = __fmul_rn(dB, dB);
    float sqmin = fminf(sqA, sqB);
    const float score_max = -__fdiv_rn(sqmin, two_s2);

    // window: e > -24
    const float rr  = sqrtf(sqmin + 24.0f * two_s2);
    int klo = lower(tval - rr);
    int khi = lower(tval + rr) - 1;

    // union over the warp's 8 consecutive rows (keeps all lanes convergent)
    int wlo = __reduce_min_sync(0xFFFFFFFFu, klo);
    int whi = __reduce_max_sync(0xFFFFFFFFu, khi);

    const float4* __restrict__ h4 = (const float4*)h;
    const size_t  bOff = (size_t)b * T;

    float  l = 0.0f;
    float4 acc[5];
    #pragma unroll
    for (int j = 0; j < 5; ++j) acc[j] = make_float4(0.f, 0.f, 0.f, 0.f);

    // chunk of 4 k's: lane f computes the faithful weight for k0+f (own row),
    // quad-shuffles, then each lane accumulates its 5 float4 columns for all 4.
    for (int k0 = wlo; k0 <= whi; k0 += 4) {
        float dt = __fsub_rn(tval, c_sh[k0 + f]);
        float sq = __fmul_rn(dt, dt);
        float sc = -__fdiv_rn(sq, two_s2);
        float e  = __fsub_rn(sc, score_max);
        float w0 = __expf(e);                          // k = k0 + f
        float w1 = __shfl_xor_sync(0xFFFFFFFFu, w0, 1); // k = k0 + (f^1)
        float w2 = __shfl_xor_sync(0xFFFFFFFFu, w0, 2); // k = k0 + (f^2)
        float w3 = __shfl_xor_sync(0xFFFFFFFFu, w1, 2); // k = k0 + (f^3)

        int i0 = i_sh[k0 + f];
        int i1 = i_sh[k0 + (f ^ 1)];
        int i2 = i_sh[k0 + (f ^ 2)];
        int i3 = i_sh[k0 + (f ^ 3)];

        l += ((w0 + w1) + (w2 + w3));

        const float4* r0 = h4 + (bOff + i0) * DF4 + f;
        const float4* r1 = h4 + (bOff + i1) * DF4 + f;
        const float4* r2 = h4 + (bOff + i2) * DF4 + f;
        const float4* r3 = h4 + (bOff + i3) * DF4 + f;
        #pragma unroll
        for (int j = 0; j < 5; ++j) {
            float4 v0 = r0[4 * j];
            acc[j].x += w0 * v0.x; acc[j].y += w0 * v0.y;
            acc[j].z += w0 * v0.z; acc[j].w += w0 * v0.w;
            float4 v1 = r1[4 * j];
            acc[j].x += w1 * v1.x; acc[j].y += w1 * v1.y;
            acc[j].z += w1 * v1.z; acc[j].w += w1 * v1.w;
            float4 v2 = r2[4 * j];
            acc[j].x += w2 * v2.x; acc[j].y += w2 * v2.y;
            acc[j].z += w2 * v2.z; acc[j].w += w2 * v2.w;
            float4 v3 = r3[4 * j];
            acc[j].x += w3 * v3.x; acc[j].y += w3 * v3.y;
            acc[j].z += w3 * v3.z; acc[j].w += w3 * v3.w;
        }
    }

    const float linv = 1.0f / l;
    float4* o = (float4*)out + ((size_t)b * SIZE + s) * DF4 + f;
    #pragma unroll
    for (int j = 0; j < 5; ++j) {
        float4 v;
        v.x = acc[j].x * linv; v.y = acc[j].y * linv;
        v.z = acc[j].z * linv; v.w = acc[j].w * linv;
        o[4 * j] = v;
    }
}

// ---------------------------------------------------------------------------
extern "C" void kernel_launch(void* const* d_in, const int* in_sizes, int n_in,
                              void* d_out, int out_size) {
    const float* h     = (const float*)d_in[0];  // [16,1024,80]
    const float* d     = (const float*)d_in[1];  // [16,1024]
    const float* sigma = (const float*)d_in[2];  // [1]

    prep_kernel<<<BS, T>>>(d);
    dim3 grid(SIZE / RPB, BS);
    alignment_kernel<<<grid, TPB>>>(h, sigma, (float*)d_out);
}